// round 16
// baseline (speedup 1.0000x reference)
#include <cuda_runtime.h>
#include <cuda_fp16.h>
#include <cuda_fp8.h>
#include <math.h>
#include <stdint.h>

#define NN 100000
#define NC 64
#define NE 3200000
#define NB 400          // blocks for node-elementwise kernels (256 thr)
#define NCH 98          // ceil(NN/1024) scan chunks

// ---------------- scratch (static __device__ — no allocations allowed) ------
__device__ float   g_seed  [(size_t)NN * NC];
__device__ uint8_t g_seed_q[(size_t)NN * NC];     // e4m3
__device__ float   g_propA [(size_t)NN * NC];
__device__ float   g_propB [(size_t)NN * NC];
__device__ uint8_t g_propAq[(size_t)NN * NC];     // e4m3
__device__ uint8_t g_propBq[(size_t)NN * NC];     // e4m3
__device__ float   g_bctx  [(size_t)NN * NC];
__device__ float   g_mass[NN], g_ent[NN];
__device__ float   g_sgate[NN], g_rgate[NN], g_anchor[NN], g_selb[NN], g_den[NN];
__device__ int     g_hist[NN];
__device__ int     g_off[NN + 1];
__device__ int     g_cur[NN];
__device__ int2    g_edge[NE];                    // {src, half2(w, w*sgate[src])}
__device__ int     g_csum[NCH], g_cbase[NCH];
__device__ float   g_pmass[NB], g_pclust[NB];
__device__ float   g_scal[4];                     // 2: conf_sum, 3: graph_scale
__device__ float   g_gp[NC];

// ---------------- helpers ---------------------------------------------------
__device__ __forceinline__ float wsum(float v) {
    #pragma unroll
    for (int o = 16; o; o >>= 1) v += __shfl_xor_sync(0xffffffffu, v, o);
    return v;
}
__device__ __forceinline__ void wtop2(float& m1, float& m2) {
    #pragma unroll
    for (int o = 16; o; o >>= 1) {
        float o1 = __shfl_xor_sync(0xffffffffu, m1, o);
        float o2 = __shfl_xor_sync(0xffffffffu, m2, o);
        float hi = fmaxf(m1, o1);
        float lo = fmaxf(fminf(m1, o1), fmaxf(m2, o2));
        m1 = hi; m2 = lo;
    }
}
__device__ __forceinline__ float clamp01(float x) { return fminf(fmaxf(x, 0.f), 1.f); }
__device__ __forceinline__ float sigmoidf(float x) { return 1.f / (1.f + expf(-x)); }

// 4 × e4m3 (packed u32, ch0 = low byte) -> 4 floats  (cuda_fp8.h intrinsics)
__device__ __forceinline__ float4 fp8x4_to_float4(uint32_t v) {
    __nv_fp8x2_storage_t lo = (__nv_fp8x2_storage_t)(v & 0xffffu);
    __nv_fp8x2_storage_t hi = (__nv_fp8x2_storage_t)(v >> 16);
    __half2_raw h01 = __nv_cvt_fp8x2_to_halfraw2(lo, __NV_E4M3);
    __half2_raw h23 = __nv_cvt_fp8x2_to_halfraw2(hi, __NV_E4M3);
    float2 f01 = __half22float2(*reinterpret_cast<__half2*>(&h01));
    float2 f23 = __half22float2(*reinterpret_cast<__half2*>(&h23));
    return make_float4(f01.x, f01.y, f23.x, f23.y);
}
// 4 floats -> packed 4 × e4m3 (c0 in lowest byte)
__device__ __forceinline__ uint32_t float4_to_fp8x4(float c0, float c1, float c2, float c3) {
    __nv_fp8x2_storage_t lo =
        __nv_cvt_float2_to_fp8x2(make_float2(c0, c1), __NV_SATFINITE, __NV_E4M3);
    __nv_fp8x2_storage_t hi =
        __nv_cvt_float2_to_fp8x2(make_float2(c2, c3), __NV_SATFINITE, __NV_E4M3);
    return (uint32_t)lo | ((uint32_t)hi << 16);
}
__device__ __forceinline__ unsigned short float2_to_fp8x2(float c0, float c1) {
    return (unsigned short)
        __nv_cvt_float2_to_fp8x2(make_float2(c0, c1), __NV_SATFINITE, __NV_E4M3);
}

// ---------------- kernels ---------------------------------------------------
// seed = relu(logits); mass/entropy; partial sums; zero hist/gp/scal
__global__ void __launch_bounds__(256) k_seed(const float* __restrict__ logits,
                                              const float* __restrict__ sf) {
    __shared__ float sm_mass[8], sm_clust[8];
    int t = blockIdx.x * blockDim.x + threadIdx.x;
    if (t < NN) g_hist[t] = 0;
    if (t < NC) g_gp[t] = 0.f;
    if (t < 4)  g_scal[t] = 0.f;
    int warp = t >> 5;
    int lane = threadIdx.x & 31;
    int wib  = threadIdx.x >> 5;
    int nw   = (gridDim.x * blockDim.x) >> 5;
    float lmass = 0.f, lclust = 0.f;
    for (int n = warp; n < NN; n += nw) {
        float2 lg = reinterpret_cast<const float2*>(logits + (size_t)n * NC)[lane];
        float2 s  = make_float2(fmaxf(lg.x, 0.f), fmaxf(lg.y, 0.f));
        reinterpret_cast<float2*>(g_seed + (size_t)n * NC)[lane] = s;
        reinterpret_cast<unsigned short*>(g_seed_q + (size_t)n * NC)[lane] =
            float2_to_fp8x2(s.x, s.y);
        float mass = wsum(s.x + s.y);
        float inv  = 1.f / (mass + 1e-8f);
        float nx = s.x * inv, ny = s.y * inv;
        float e   = -(nx * logf(nx + 1e-8f) + ny * logf(ny + 1e-8f));
        float ent = wsum(e);
        if (lane == 0) {
            g_mass[n] = mass; g_ent[n] = ent;
            lmass += mass; lclust += sf[2 * n + 1];
        }
    }
    if (lane == 0) { sm_mass[wib] = lmass; sm_clust[wib] = lclust; }
    __syncthreads();
    if (threadIdx.x == 0) {
        float m = 0.f, c = 0.f;
        #pragma unroll
        for (int i = 0; i < 8; i++) { m += sm_mass[i]; c += sm_clust[i]; }
        g_pmass[blockIdx.x] = m; g_pclust[blockIdx.x] = c;
    }
}

// confidence, gates, anchor, selective-base; global prior numerator & conf sum
__global__ void __launch_bounds__(256) k_conf(const float* __restrict__ sf) {
    __shared__ float sm[256];
    float acc = 0.f;
    for (int i = threadIdx.x; i < NB; i += 256) acc += g_pmass[i];
    sm[threadIdx.x] = acc;
    __syncthreads();
    for (int o = 128; o; o >>= 1) {
        if (threadIdx.x < o) sm[threadIdx.x] += sm[threadIdx.x + o];
        __syncthreads();
    }
    float scale = fmaxf(sm[0] * (1.f / (float)NN), 1e-8f);
    __syncthreads();

    int warp = (blockIdx.x * blockDim.x + threadIdx.x) >> 5;
    int lane = threadIdx.x & 31;
    int nw   = (gridDim.x * blockDim.x) >> 5;
    const float invlog = 1.f / logf(64.f);
    float2 gpacc = make_float2(0.f, 0.f);
    float lconf = 0.f;
    for (int n = warp; n < NN; n += nw) {
        float mass = g_mass[n], ent = g_ent[n];
        float cert = 1.f - ent * invlog;
        float mag  = tanhf(mass / scale);
        float conf = clamp01(0.5f * cert + 0.5f * mag);
        float2 s = reinterpret_cast<const float2*>(g_seed + (size_t)n * NC)[lane];
        gpacc.x += conf * s.x;  gpacc.y += conf * s.y;
        if (lane == 0) {
            lconf += conf;
            g_sgate[n]  = sigmoidf(8.f * (conf - 0.55f));
            g_rgate[n]  = sigmoidf(8.f * (0.5f - conf));
            g_anchor[n] = fminf(fmaxf(0.6f + 0.2f * conf, 0.f), 0.995f);
            float ld = clamp01(1.f - sf[2 * n + 0]);
            float lc = clamp01(1.f - sf[2 * n + 1]);
            g_selb[n] = (1.f - conf) + 0.25f * ld + 0.2f * lc;
        }
    }
    atomicAdd(&g_gp[2 * lane + 0], gpacc.x);
    atomicAdd(&g_gp[2 * lane + 1], gpacc.y);
    if (lane == 0) atomicAdd(&g_scal[2], lconf);
}

// histogram of dst + finalize global prior & graph_scale
__global__ void k_hist(const int* __restrict__ dst) {
    if (blockIdx.x == 0 && threadIdx.x == 0) {
        float c = 0.f;
        for (int i = 0; i < NB; i++) c += g_pclust[i];
        g_scal[3] = fminf(fmaxf(1.f - c * (1.f / (float)NN), 0.2f), 1.f);
    }
    if (blockIdx.x == 1 && threadIdx.x < NC) {
        g_gp[threadIdx.x] /= fmaxf(g_scal[2], 1e-8f);
    }
    int e = blockIdx.x * blockDim.x + threadIdx.x;
    int stride = gridDim.x * blockDim.x;
    for (; e < NE; e += stride) atomicAdd(&g_hist[dst[e]], 1);
}

// ---- parallel 3-phase exclusive scan of g_hist -> g_off, g_cur -------------
__global__ void __launch_bounds__(1024) k_scan1() {
    __shared__ int wsums[32];
    int tid = threadIdx.x;
    int lane = tid & 31;
    int i = blockIdx.x * 1024 + tid;
    int v = (i < NN) ? g_hist[i] : 0;
    int x = v;
    #pragma unroll
    for (int o = 1; o < 32; o <<= 1) {
        int t = __shfl_up_sync(0xffffffffu, x, o);
        if (lane >= o) x += t;
    }
    if (lane == 31) wsums[tid >> 5] = x;
    __syncthreads();
    if (tid < 32) {
        int s = wsums[tid];
        #pragma unroll
        for (int o = 1; o < 32; o <<= 1) {
            int t = __shfl_up_sync(0xffffffffu, s, o);
            if (lane >= o) s += t;
        }
        wsums[tid] = s;
    }
    __syncthreads();
    int base = (tid >= 32) ? wsums[(tid >> 5) - 1] : 0;
    int inc = x + base;
    if (i < NN) g_off[i] = inc - v;
    if (tid == 1023) g_csum[blockIdx.x] = inc;
}
__global__ void k_scan2() {
    __shared__ int sh[128];
    int tid = threadIdx.x;
    int v = (tid < NCH) ? g_csum[tid] : 0;
    sh[tid] = v;
    __syncthreads();
    for (int o = 1; o < 128; o <<= 1) {
        int t = (tid >= o) ? sh[tid - o] : 0;
        __syncthreads();
        sh[tid] += t;
        __syncthreads();
    }
    if (tid < NCH) g_cbase[tid] = sh[tid] - v;
}
__global__ void k_scan3() {
    int i = blockIdx.x * blockDim.x + threadIdx.x;
    if (i < NN) {
        int off = g_off[i] + g_cbase[i >> 10];
        g_off[i] = off;
        g_cur[i] = off;
    }
    if (i == 0) g_off[NN] = NE;
}

// scatter into dst-sorted 8B edge records {src, half2(w, w*sgate[src])}
__global__ void k_scat(const int* __restrict__ src, const int* __restrict__ dst,
                       const float* __restrict__ w) {
    int e = blockIdx.x * blockDim.x + threadIdx.x;
    int stride = gridDim.x * blockDim.x;
    for (; e < NE; e += stride) {
        int d = dst[e];
        int s = src[e];
        float wv = w[e];
        float sg = g_sgate[s];
        int pos = atomicAdd(&g_cur[d], 1);
        __half2 hp = __halves2half2(__float2half_rn(wv),
                                    __float2half_rn(wv * sg));
        int2 rec;
        rec.x = s;
        rec.y = *reinterpret_cast<int*>(&hp);
        g_edge[pos] = rec;
    }
}

// ---------------- fused gather-SPMM + epilogue -------------------------------
// Warp per dst node. Half-warp per edge. Records are staged through shared
// memory in 32-edge chunks (1 coalesced LDG.64 per chunk instead of 16
// broadcast LDGs) to cut L1TEX queue pressure; row gathers keep 4 independent
// chains in flight. Edge accumulation order identical to previous version.
// MODE 0: x=seed_q  (w2), den & bctx, update with p=seed  -> propA (+fp8)
// MODE 1: x=prop_q  (w2), update with p=prop[bufin]       -> prop[bufin^1]
// MODE 3: x=prop_q  (w),  prop_ctx + fused accept/blend   -> out
template <int MODE>
__global__ void __launch_bounds__(256) k_fused(int bufin, float* __restrict__ outp) {
    __shared__ int2 s_rec[8][32];
    int warp = (blockIdx.x * blockDim.x + threadIdx.x) >> 5;
    if (warp >= NN) return;
    int lane = threadIdx.x & 31;
    int wib  = (threadIdx.x >> 5);
    int g    = lane & 15;
    int half = lane >> 4;        // 0 or 1: which edge of the pair
    const uint32_t* __restrict__ xq =
        (MODE == 0) ? reinterpret_cast<const uint32_t*>(g_seed_q)
                    : reinterpret_cast<const uint32_t*>(bufin ? g_propBq : g_propAq);
    int beg = g_off[warp], end = g_off[warp + 1];
    float a0 = 0.f, a1 = 0.f, a2 = 0.f, a3 = 0.f;
    float b0 = 0.f, b1 = 0.f, b2 = 0.f, b3 = 0.f;
    float dacc = 0.f;
    float dmask = (g == 0) ? 1.f : 0.f;   // one lane per half counts each edge

    int e = beg;
    // chunked main loop: 32 edges per chunk; records staged via smem
    for (; e + 32 <= end; e += 32) {
        s_rec[wib][lane] = __ldg(&g_edge[e + lane]);
        __syncwarp();
        #pragma unroll
        for (int t = 0; t < 4; t++) {           // 4 batches × 4 chains × 2 edges
            int2 rec[4];
            #pragma unroll
            for (int c = 0; c < 4; c++)
                rec[c] = s_rec[wib][t * 8 + 2 * c + half];
            uint32_t v[4];
            #pragma unroll
            for (int c = 0; c < 4; c++)
                v[c] = __ldg(&xq[(size_t)rec[c].x * 16 + g]);
            #pragma unroll
            for (int c = 0; c < 4; c++) {
                __half2 wp = *reinterpret_cast<__half2*>(&rec[c].y);
                float w  = __low2float(wp);
                float w2 = __high2float(wp);
                float4 f = fp8x4_to_float4(v[c]);
                float wa = (MODE == 3) ? w : w2;
                a0 = fmaf(wa, f.x, a0); a1 = fmaf(wa, f.y, a1);
                a2 = fmaf(wa, f.z, a2); a3 = fmaf(wa, f.w, a3);
                if (MODE == 0) {
                    dacc += dmask * w2;
                    b0 = fmaf(w, f.x, b0); b1 = fmaf(w, f.y, b1);
                    b2 = fmaf(w, f.z, b2); b3 = fmaf(w, f.w, b3);
                }
            }
        }
        __syncwarp();
    }
    // mid tail: up to 3 quads of 8 edges with global 4-chain loads
    for (; e + 8 <= end; e += 8) {
        int2 rec[4];
        #pragma unroll
        for (int c = 0; c < 4; c++)
            rec[c] = __ldg(&g_edge[e + 2 * c + half]);
        uint32_t v[4];
        #pragma unroll
        for (int c = 0; c < 4; c++)
            v[c] = __ldg(&xq[(size_t)rec[c].x * 16 + g]);
        #pragma unroll
        for (int c = 0; c < 4; c++) {
            __half2 wp = *reinterpret_cast<__half2*>(&rec[c].y);
            float w  = __low2float(wp);
            float w2 = __high2float(wp);
            float4 f = fp8x4_to_float4(v[c]);
            float wa = (MODE == 3) ? w : w2;
            a0 = fmaf(wa, f.x, a0); a1 = fmaf(wa, f.y, a1);
            a2 = fmaf(wa, f.z, a2); a3 = fmaf(wa, f.w, a3);
            if (MODE == 0) {
                dacc += dmask * w2;
                b0 = fmaf(w, f.x, b0); b1 = fmaf(w, f.y, b1);
                b2 = fmaf(w, f.z, b2); b3 = fmaf(w, f.w, b3);
            }
        }
    }
    // tail: processed in masked pairs
    for (; e < end; e += 2) {
        int idx = e + half;
        bool valid = idx < end;
        int2 rec = __ldg(&g_edge[valid ? idx : beg]);
        __half2 wp = *reinterpret_cast<__half2*>(&rec.y);
        float w  = valid ? __low2float(wp)  : 0.f;
        float w2 = valid ? __high2float(wp) : 0.f;
        uint32_t v = __ldg(&xq[(size_t)rec.x * 16 + g]);
        float4 f = fp8x4_to_float4(v);
        float wa = (MODE == 3) ? w : w2;
        a0 = fmaf(wa, f.x, a0); a1 = fmaf(wa, f.y, a1);
        a2 = fmaf(wa, f.z, a2); a3 = fmaf(wa, f.w, a3);
        if (MODE == 0) {
            dacc += dmask * w2;
            b0 = fmaf(w, f.x, b0); b1 = fmaf(w, f.y, b1);
            b2 = fmaf(w, f.z, b2); b3 = fmaf(w, f.w, b3);
        }
    }

    a0 += __shfl_xor_sync(0xffffffffu, a0, 16);
    a1 += __shfl_xor_sync(0xffffffffu, a1, 16);
    a2 += __shfl_xor_sync(0xffffffffu, a2, 16);
    a3 += __shfl_xor_sync(0xffffffffu, a3, 16);
    if (MODE == 0) {
        b0 += __shfl_xor_sync(0xffffffffu, b0, 16);
        b1 += __shfl_xor_sync(0xffffffffu, b1, 16);
        b2 += __shfl_xor_sync(0xffffffffu, b2, 16);
        b3 += __shfl_xor_sync(0xffffffffu, b3, 16);
    }
    size_t row = (size_t)warp * NC;
    float4 s4 = *reinterpret_cast<const float4*>(g_seed + row + 4 * g);
    float m = (lane < 16) ? 1.f : 0.f;   // kill duplicate half in reductions

    if (MODE == 0 || MODE == 1) {
        float den;
        if (MODE == 0) {
            den = wsum(dacc);
            if (lane == 0) g_den[warp] = den;
        } else {
            den = g_den[warp];
        }
        const float* __restrict__ pin =
            (MODE == 0) ? g_seed : (bufin ? g_propB : g_propA);
        float4 p4 = (MODE == 0) ? s4
                  : *reinterpret_cast<const float4*>(pin + row + 4 * g);
        float4 gp4 = reinterpret_cast<const float4*>(g_gp)[g];
        float inv = 1.f / fmaxf(den, 1e-8f);
        float f0 = 0.95f * a0 * inv + 0.05f * gp4.x;
        float f1 = 0.95f * a1 * inv + 0.05f * gp4.y;
        float f2 = 0.95f * a2 * inv + 0.05f * gp4.z;
        float f3 = 0.95f * a3 * inv + 0.05f * gp4.w;
        float pf  = wsum(m * (p4.x * f0 + p4.y * f1 + p4.z * f2 + p4.w * f3));
        float pp  = wsum(m * (p4.x * p4.x + p4.y * p4.y + p4.z * p4.z + p4.w * p4.w));
        float ff  = wsum(m * (f0 * f0 + f1 * f1 + f2 * f2 + f3 * f3));
        float sfd = wsum(m * (s4.x * f0 + s4.y * f1 + s4.z * f2 + s4.w * f3));
        float ss  = wsum(m * (s4.x * s4.x + s4.y * s4.y + s4.z * s4.z + s4.w * s4.w));
        float np = fmaxf(sqrtf(pp), 1e-8f);
        float nf = fmaxf(sqrtf(ff), 1e-8f);
        float ns = fmaxf(sqrtf(ss), 1e-8f);
        float agree  = clamp01((pf  / (np * nf) + 1.f) * 0.5f);
        float sagree = clamp01((sfd / (ns * nf) + 1.f) * 0.5f);
        float sel    = clamp01(g_selb[warp] + 0.2f * sagree);
        float anchor = g_anchor[warp];
        float ug = g_rgate[warp] * sel * agree * (1.f - anchor);
        float rc = 0.15f * g_scal[3] * ug;
        float o0 = fmaxf(anchor * s4.x + (1.f - anchor) * p4.x + rc * (f0 - p4.x), 0.f);
        float o1 = fmaxf(anchor * s4.y + (1.f - anchor) * p4.y + rc * (f1 - p4.y), 0.f);
        float o2 = fmaxf(anchor * s4.z + (1.f - anchor) * p4.z + rc * (f2 - p4.z), 0.f);
        float o3 = fmaxf(anchor * s4.w + (1.f - anchor) * p4.w + rc * (f3 - p4.w), 0.f);
        int outb = (MODE == 0) ? 0 : (bufin ^ 1);
        float*   pout_f = outb ? g_propB  : g_propA;
        uint8_t* pout_q = outb ? g_propBq : g_propAq;
        if (lane < 16) {
            *reinterpret_cast<float4*>(pout_f + row + 4 * g) =
                make_float4(o0, o1, o2, o3);
            reinterpret_cast<uint32_t*>(pout_q + row)[g] =
                float4_to_fp8x4(o0, o1, o2, o3);
            if (MODE == 0)
                *reinterpret_cast<float4*>(g_bctx + row + 4 * g) =
                    make_float4(b0, b1, b2, b3);
        }
    } else {
        // MODE 3: accept & blend. a0..a3 = prop_ctx cols.
        const float* __restrict__ pin = bufin ? g_propB : g_propA;
        float4 p4  = *reinterpret_cast<const float4*>(pin + row + 4 * g);
        float4 bc4 = *reinterpret_cast<const float4*>(g_bctx + row + 4 * g);
        float sbc = wsum(m * (s4.x * bc4.x + s4.y * bc4.y + s4.z * bc4.z + s4.w * bc4.w));
        float ss  = wsum(m * (s4.x * s4.x + s4.y * s4.y + s4.z * s4.z + s4.w * s4.w));
        float bb  = wsum(m * (bc4.x * bc4.x + bc4.y * bc4.y + bc4.z * bc4.z + bc4.w * bc4.w));
        float ppc = wsum(m * (p4.x * a0 + p4.y * a1 + p4.z * a2 + p4.w * a3));
        float pp  = wsum(m * (p4.x * p4.x + p4.y * p4.y + p4.z * p4.z + p4.w * p4.w));
        float cc  = wsum(m * (a0 * a0 + a1 * a1 + a2 * a2 + a3 * a3));
        float ms  = wsum(m * (s4.x + s4.y + s4.z + s4.w));
        float mp  = wsum(m * (p4.x + p4.y + p4.z + p4.w));
        // lane-local top2 of 4, masked to -inf on dup half, then warp top2
        float sa = fmaxf(s4.x, s4.y), sb = fminf(s4.x, s4.y);
        float sc = fmaxf(s4.z, s4.w), sd = fminf(s4.z, s4.w);
        float s1 = fmaxf(sa, sc);
        float s2 = fmaxf(fminf(sa, sc), fmaxf(sb, sd));
        float pa = fmaxf(p4.x, p4.y), pb = fminf(p4.x, p4.y);
        float pc_ = fmaxf(p4.z, p4.w), pd = fminf(p4.z, p4.w);
        float p1 = fmaxf(pa, pc_);
        float p2 = fmaxf(fminf(pa, pc_), fmaxf(pb, pd));
        if (lane >= 16) { s1 = -1e30f; s2 = -1e30f; p1 = -1e30f; p2 = -1e30f; }
        wtop2(s1, s2);
        wtop2(p1, p2);
        float ns_ = fmaxf(sqrtf(ss), 1e-8f);
        float nbc = fmaxf(sqrtf(bb), 1e-8f);
        float np_ = fmaxf(sqrtf(pp), 1e-8f);
        float npc = fmaxf(sqrtf(cc), 1e-8f);
        float lqb = clamp01((sbc / (ns_ * nbc) + 1.f) * 0.5f);
        float lqp = clamp01((ppc / (np_ * npc) + 1.f) * 0.5f);
        float mb  = (s1 - s2) / (ms + 1e-8f);
        float mpg = (p1 - p2) / (mp + 1e-8f);
        // clustering term cancels in qp - qb
        float accept = sigmoidf(12.f * ((0.7f * lqp + 0.2f * mpg) -
                                        (0.7f * lqb + 0.2f * mb)));
        if (lane < 16) {
            float o0 = accept * p4.x + (1.f - accept) * s4.x;
            float o1 = accept * p4.y + (1.f - accept) * s4.y;
            float o2 = accept * p4.z + (1.f - accept) * s4.z;
            float o3 = accept * p4.w + (1.f - accept) * s4.w;
            *reinterpret_cast<float4*>(outp + row + 4 * g) =
                make_float4(o0, o1, o2, o3);
        }
    }
}

// ---------------- launch ----------------------------------------------------
extern "C" void kernel_launch(void* const* d_in, const int* in_sizes, int n_in,
                              void* d_out, int out_size) {
    (void)in_sizes; (void)n_in; (void)out_size;
    const float* logits = (const float*)d_in[0];
    const int*   esrc   = (const int*)d_in[1];
    const int*   edst   = (const int*)d_in[2];
    const float* ew     = (const float*)d_in[3];
    const float* sf     = (const float*)d_in[4];
    float* out = (float*)d_out;

    const int NODE_BLOCKS = (NN + 7) / 8;   // warp per node, 8 warps/block

    k_seed<<<NB, 256>>>(logits, sf);
    k_conf<<<NB, 256>>>(sf);
    k_hist<<<(NE + 511) / 512, 512>>>(edst);
    k_scan1<<<NCH, 1024>>>();
    k_scan2<<<1, 128>>>();
    k_scan3<<<(NN + 255) / 256, 256>>>();
    k_scat<<<(NE + 511) / 512, 512>>>(esrc, edst, ew);

    k_fused<0><<<NODE_BLOCKS, 256>>>(0, out);  // seed gather + update1 -> A
    k_fused<1><<<NODE_BLOCKS, 256>>>(0, out);  // A -> update2 -> B
    k_fused<1><<<NODE_BLOCKS, 256>>>(1, out);  // B -> update3 -> A
    k_fused<3><<<NODE_BLOCKS, 256>>>(0, out);  // prop_ctx(A) + accept -> out
}